// round 15
// baseline (speedup 1.0000x reference)
#include <cuda_runtime.h>
#include <cuda_fp16.h>
#include <cstdint>

#define BB 16
#define CC 128
#define DD 32
#define NN 2048
#define SQRT_LOG2E 1.2011224087864498f

// ---------------- device scratch (static) ----------------
__device__ __half g_qh[BB * NN * DD];   // qT[b][n][d], *sqrt(log2e), fp16
__device__ __half g_v [BB * CC * NN];   // v[b][c][n], fp16
__device__ float  g_rl[BB * NN];        // log2(rowsum)

// ---------------- helpers ----------------
__device__ __forceinline__ float ex2f(float x) {
    float y; asm("ex2.approx.ftz.f32 %0, %1;" : "=f"(y) : "f"(x)); return y;
}
__device__ __forceinline__ float lg2f(float x) {
    float y; asm("lg2.approx.f32 %0, %1;" : "=f"(y) : "f"(x)); return y;
}
__device__ __forceinline__ uint32_t ex2h2(uint32_t x) {
    uint32_t y; asm("ex2.approx.f16x2 %0, %1;" : "=r"(y) : "r"(x)); return y;
}
__device__ __forceinline__ void mma16h(float c[4],
                                       uint32_t a0, uint32_t a1, uint32_t a2, uint32_t a3,
                                       uint32_t b0, uint32_t b1) {
    asm volatile(
        "mma.sync.aligned.m16n8k16.row.col.f32.f16.f16.f32 "
        "{%0,%1,%2,%3}, {%4,%5,%6,%7}, {%8,%9}, {%0,%1,%2,%3};"
        : "+f"(c[0]), "+f"(c[1]), "+f"(c[2]), "+f"(c[3])
        : "r"(a0), "r"(a1), "r"(a2), "r"(a3), "r"(b0), "r"(b1));
}
__device__ __forceinline__ void ldsm4(uint32_t r[4], uint32_t addr) {
    asm volatile("ldmatrix.sync.aligned.m8n8.x4.shared.b16 {%0,%1,%2,%3}, [%4];"
        : "=r"(r[0]), "=r"(r[1]), "=r"(r[2]), "=r"(r[3]) : "r"(addr));
}
__device__ __forceinline__ void ldsm4t(uint32_t r[4], uint32_t addr) {
    asm volatile("ldmatrix.sync.aligned.m8n8.x4.trans.shared.b16 {%0,%1,%2,%3}, [%4];"
        : "=r"(r[0]), "=r"(r[1]), "=r"(r[2]), "=r"(r[3]) : "r"(addr));
}
__device__ __forceinline__ uint32_t smem_u32(const void* p) {
    uint32_t a;
    asm("{ .reg .u64 t; cvta.to.shared.u64 t, %1; cvt.u32.u64 %0, t; }" : "=r"(a) : "l"(p));
    return a;
}
__device__ __forceinline__ void cpa16(uint32_t dst, const void* src) {
    asm volatile("cp.async.cg.shared.global [%0], [%1], 16;" :: "r"(dst), "l"(src));
}
#define CPA_COMMIT() asm volatile("cp.async.commit_group;" ::: "memory")
#define CPA_WAIT(n)  asm volatile("cp.async.wait_group %0;" :: "n"(n) : "memory")

// ======================================================================
// k1: q = wq@x (scaled, fp16) ; v = wv@x + bv (fp16) — fp16 mma compute
// (R11 version — measured 26.8us)
// ======================================================================
__global__ __launch_bounds__(640) void k_qv(const float* __restrict__ x,
                                            const float* __restrict__ wq,
                                            const float* __restrict__ wv,
                                            const float* __restrict__ bv) {
    extern __shared__ char smc[];
    __half* xh   = (__half*)smc;              // [n][c] stride 136
    __half* wsh  = (__half*)(smc + 34816);    // [r][c] stride 136
    float*  qb   = (float*)(smc + 78336);     // 32x129
    float*  bv_s = (float*)(smc + 94848);
    const int b  = blockIdx.y;
    const int n0 = blockIdx.x * 128;
    const int tid = threadIdx.x;
    const float* xb = x + (size_t)b * CC * NN;

    for (int i = tid; i < CC * 128; i += 640) {
        int c = i >> 7, n = i & 127;
        xh[n * 136 + c] = __float2half_rn(xb[(size_t)c * NN + n0 + n]);
    }
    for (int i = tid; i < 160 * 128; i += 640) {
        int r = i >> 7, c = i & 127;
        float w = (r < DD) ? wq[r * CC + c] : wv[(r - DD) * CC + c];
        wsh[r * 136 + c] = __float2half_rn(w);
    }
    if (tid < CC) bv_s[tid] = bv[tid];
    __syncthreads();

    const int w = tid >> 5, lane = tid & 31;
    const int rg = w >> 2, cg = w & 3;
    const int row0 = rg * 32, col0 = cg * 32;
    const int qr = lane >> 2, ql = lane & 3;
    const uint32_t ws_u = smem_u32(wsh), xh_u = smem_u32(xh);
    const int la = ((lane >> 3) & 1) * 8 + (lane & 7);
    const int lc = (lane >> 4) * 8;
    const int lbr = (lane >> 4) * 8 + (lane & 7);
    const int lbc = ((lane >> 3) & 1) * 8;

    float acc[2][4][4] = {};
#pragma unroll
    for (int ks = 0; ks < 8; ++ks) {
        const int k0 = ks * 16;
        uint32_t A[2][4], Bp[2][4];
#pragma unroll
        for (int mi = 0; mi < 2; ++mi)
            ldsm4(A[mi], ws_u + ((row0 + mi * 16 + la) * 136 + k0 + lc) * 2);
#pragma unroll
        for (int p = 0; p < 2; ++p)
            ldsm4(Bp[p], xh_u + ((col0 + p * 16 + lbr) * 136 + k0 + lbc) * 2);
#pragma unroll
        for (int mi = 0; mi < 2; ++mi)
#pragma unroll
            for (int ni = 0; ni < 4; ++ni)
                mma16h(acc[mi][ni], A[mi][0], A[mi][1], A[mi][2], A[mi][3],
                       Bp[ni >> 1][(ni & 1) * 2], Bp[ni >> 1][(ni & 1) * 2 + 1]);
    }

    if (rg == 0) {
#pragma unroll
        for (int mi = 0; mi < 2; ++mi) {
            int d = mi * 16 + qr;
#pragma unroll
            for (int ni = 0; ni < 4; ++ni) {
                int col = col0 + ni * 8 + 2 * ql;
                qb[d * 129 + col]           = acc[mi][ni][0] * SQRT_LOG2E;
                qb[d * 129 + col + 1]       = acc[mi][ni][1] * SQRT_LOG2E;
                qb[(d + 8) * 129 + col]     = acc[mi][ni][2] * SQRT_LOG2E;
                qb[(d + 8) * 129 + col + 1] = acc[mi][ni][3] * SQRT_LOG2E;
            }
        }
    } else {
#pragma unroll
        for (int mi = 0; mi < 2; ++mi) {
            int rv = row0 - DD + mi * 16 + qr;
            float b0v = bv_s[rv], b1v = bv_s[rv + 8];
#pragma unroll
            for (int ni = 0; ni < 4; ++ni) {
                int col = col0 + ni * 8 + 2 * ql;
                *(half2*)&g_v[((size_t)b * CC + rv) * NN + n0 + col] =
                    __floats2half2_rn(acc[mi][ni][0] + b0v, acc[mi][ni][1] + b0v);
                *(half2*)&g_v[((size_t)b * CC + rv + 8) * NN + n0 + col] =
                    __floats2half2_rn(acc[mi][ni][2] + b1v, acc[mi][ni][3] + b1v);
            }
        }
    }
    __syncthreads();
    for (int i = tid; i < 128 * 16; i += 640) {
        int n = i >> 4, d2 = (i & 15) << 1;
        *(half2*)&g_qh[((size_t)b * NN + n0 + n) * DD + d2] =
            __floats2half2_rn(qb[d2 * 129 + n], qb[(d2 + 1) * 129 + n]);
    }
}

// ======================================================================
// k2: rl[n] = log2( sum_m exp2(E[n,m]) ), fp16 mma + ldmatrix, fp32 ex2.
// (fp32 exp REQUIRED — fp16 exp biases row sums low, does not cancel.)
// ======================================================================
__global__ __launch_bounds__(512, 2) void k_rowsum() {
    extern __shared__ float sm[];
    float*  red  = sm;
    __half* qn_h = (__half*)(sm + 128);
    __half* qm0  = qn_h + 128 * 40;
    __half* qm1  = qm0 + 128 * 40;

    const int tid = threadIdx.x, w = tid >> 5, lane = tid & 31;
    const int row0 = (w & 3) * 32, col0 = (w >> 2) * 32;
    const int b = blockIdx.y, n0 = blockIdx.x * 128;
    const uint32_t qn_u = smem_u32(qn_h), qm0u = smem_u32(qm0), qm1u = smem_u32(qm1);
    const int la = ((lane >> 3) & 1) * 8 + (lane & 7);
    const int lc = (lane >> 4) * 8;
    const int lbr = (lane >> 4) * 8 + (lane & 7);
    const int lbc = ((lane >> 3) & 1) * 8;

    if (tid < 128) red[tid] = 0.f;
    {
        int r = tid >> 2, j = (tid & 3) << 3;
        cpa16(qn_u + (r * 40 + j) * 2, &g_qh[((size_t)b * NN + n0 + r) * DD + j]);
    }
    CPA_COMMIT();
    {
        int r = tid >> 2, j = (tid & 3) << 3;
        cpa16(qm0u + (r * 40 + j) * 2, &g_qh[((size_t)b * NN + r) * DD + j]);
    }
    CPA_COMMIT();

    float racc[2][2] = {};
    for (int mt = 0; mt < NN / 128; ++mt) {
        const uint32_t qmu = (mt & 1) ? qm1u : qm0u;
        const uint32_t qmnu = (mt & 1) ? qm0u : qm1u;
        CPA_WAIT(0);
        __syncthreads();
        if (mt + 1 < NN / 128) {
            int r = tid >> 2, j = (tid & 3) << 3;
            cpa16(qmnu + (r * 40 + j) * 2,
                  &g_qh[((size_t)b * NN + (mt + 1) * 128 + r) * DD + j]);
            CPA_COMMIT();
        }

        float e[2][4][4] = {};
#pragma unroll
        for (int ks = 0; ks < 2; ++ks) {
            const int k0 = ks * 16;
            uint32_t A[2][4], Bp[2][4];
#pragma unroll
            for (int mi = 0; mi < 2; ++mi)
                ldsm4(A[mi], qn_u + ((row0 + mi * 16 + la) * 40 + k0 + lc) * 2);
#pragma unroll
            for (int p = 0; p < 2; ++p)
                ldsm4(Bp[p], qmu + ((col0 + p * 16 + lbr) * 40 + k0 + lbc) * 2);
#pragma unroll
            for (int mi = 0; mi < 2; ++mi)
#pragma unroll
                for (int ni = 0; ni < 4; ++ni)
                    mma16h(e[mi][ni], A[mi][0], A[mi][1], A[mi][2], A[mi][3],
                           Bp[ni >> 1][(ni & 1) * 2], Bp[ni >> 1][(ni & 1) * 2 + 1]);
        }
#pragma unroll
        for (int mi = 0; mi < 2; ++mi)
#pragma unroll
            for (int ni = 0; ni < 4; ++ni) {
                racc[mi][0] += ex2f(e[mi][ni][0]) + ex2f(e[mi][ni][1]);
                racc[mi][1] += ex2f(e[mi][ni][2]) + ex2f(e[mi][ni][3]);
            }
    }

    const int qr = lane >> 2, ql = lane & 3;
#pragma unroll
    for (int mi = 0; mi < 2; ++mi)
#pragma unroll
        for (int h = 0; h < 2; ++h) {
            float v = racc[mi][h];
            v += __shfl_xor_sync(0xffffffffu, v, 1);
            v += __shfl_xor_sync(0xffffffffu, v, 2);
            racc[mi][h] = v;
        }
    if (ql == 0) {
        atomicAdd(&red[row0 + qr],          racc[0][0]);
        atomicAdd(&red[row0 + qr + 8],      racc[0][1]);
        atomicAdd(&red[row0 + 16 + qr],     racc[1][0]);
        atomicAdd(&red[row0 + 16 + qr + 8], racc[1][1]);
    }
    __syncthreads();
    if (tid < 128) g_rl[(size_t)b * NN + n0 + tid] = lg2f(red[tid]);
}

// ======================================================================
// k3: fused attention + epilogue. 256 threads, m-tile 64, n-tile 128,
// 3 CTAs/SM (smem 70656 B, single-buffered vs, R9-style 3 syncs/iter).
// smem bytes:
//   header @0 (2048): csum 64f, cinv 64f, A_s 128f, S_s 128f, rl 128f
//   qm_h @2048  (64x40 h  = 5120)
//   qn_h @7168  (128x40 h = 10240)
//   vs   @17408 (128x136 h = 34816)  epi overlay: wt_h [cout][cin] str 136
//   pn_h @52224 (128x72 h = 18432)   epi overlay: xm_h [m][c] str 136 (17408)
// ======================================================================
__global__ __launch_bounds__(256, 3) void k_attn(const float* __restrict__ x,
                                                 const float* __restrict__ wt,
                                                 const float* __restrict__ bt,
                                                 const float* __restrict__ gamma,
                                                 const float* __restrict__ beta,
                                                 const float* __restrict__ mean,
                                                 const float* __restrict__ var,
                                                 float* __restrict__ out) {
    extern __shared__ float sm[];
    char* smc = (char*)sm;
    float* csum_s = sm;             // 64
    float* cinv_s = sm + 64;        // 64
    float* A_s    = sm + 128;       // 128
    float* S_s    = sm + 256;       // 128
    float* rl_s   = sm + 384;       // 128
    __half* qm_h  = (__half*)(smc + 2048);
    __half* qn_h  = (__half*)(smc + 7168);
    __half* vs    = (__half*)(smc + 17408);
    __half* pn_h  = (__half*)(smc + 52224);
    __half* wt_h  = vs;                       // epilogue overlay
    __half* xm_h  = pn_h;                     // epilogue overlay

    const int tid = threadIdx.x, w = tid >> 5, lane = tid & 31;
    const int row0 = (w & 3) * 32, col0 = (w >> 2) * 32;   // col0 in {0,32}
    const int qr = lane >> 2, ql = lane & 3;
    const int b = blockIdx.y, m0 = blockIdx.x * 64;
    const uint32_t qm_u = smem_u32(qm_h), qn_u = smem_u32(qn_h);
    const uint32_t vs_u = smem_u32(vs), pn_u = smem_u32(pn_h);
    const uint32_t rl_u = smem_u32(rl_s);
    const uint32_t wt_u = vs_u, xm_u = pn_u;
    const int la = ((lane >> 3) & 1) * 8 + (lane & 7);
    const int lc = (lane >> 4) * 8;
    const int lbr = (lane >> 4) * 8 + (lane & 7);
    const int lbc = ((lane >> 3) & 1) * 8;
    const float* grl = &g_rl[(size_t)b * NN];

    if (tid < 64) csum_s[tid] = 0.f;
    if (tid >= 64 && tid < 192) {
        int c = tid - 64;
        float A = gamma[c] * rsqrtf(var[c] + 1e-5f);
        A_s[c] = A;
        S_s[c] = beta[c] + (bt[c] - mean[c]) * A;
    }
    {   // qm: 64 rows x 32 halves
        int r = tid >> 2, j = (tid & 3) << 3;
        *(uint4*)&qm_h[r * 40 + j] =
            *(const uint4*)&g_qh[((size_t)b * NN + m0 + r) * DD + j];
    }
    // prologue: G1 = {qn(0), rl(0)} ; G2 = {vs(0)}
#pragma unroll
    for (int k = 0; k < 2; ++k) {
        int idx = tid + k * 256;
        int r = idx >> 2, j = (idx & 3) << 3;
        cpa16(qn_u + (r * 40 + j) * 2, &g_qh[((size_t)b * NN + r) * DD + j]);
    }
    if (tid < 32) cpa16(rl_u + tid * 16, grl + tid * 4);
    CPA_COMMIT();
#pragma unroll
    for (int k = 0; k < 8; ++k) {
        int idx = tid + k * 256;
        int c = idx >> 4, j = (idx & 15) << 3;
        cpa16(vs_u + (c * 136 + j) * 2, &g_v[((size_t)b * CC + c) * NN + j]);
    }
    CPA_COMMIT();

    float yacc[2][4][4] = {};
    float csum[8] = {};

    for (int nt = 0; nt < NN / 128; ++nt) {
        const int nb = nt * 128;
        CPA_WAIT(1);                 // qn(nt) + rl(nt) ready (vs may fly)
        __syncthreads();             // sync1: loads visible; prev Y done w/ pn

        // ---- E = qn . qm^T (fp16): warp 32x32 ----
        float e[2][4][4] = {};
#pragma unroll
        for (int ks = 0; ks < 2; ++ks) {
            const int k0 = ks * 16;
            uint32_t A[2][4], Bp[2][4];
#pragma unroll
            for (int mi = 0; mi < 2; ++mi)
                ldsm4(A[mi], qn_u + ((row0 + mi * 16 + la) * 40 + k0 + lc) * 2);
#pragma unroll
            for (int p = 0; p < 2; ++p)
                ldsm4(Bp[p], qm_u + ((col0 + p * 16 + lbr) * 40 + k0 + lbc) * 2);
#pragma unroll
            for (int mi = 0; mi < 2; ++mi)
#pragma unroll
                for (int ni = 0; ni < 4; ++ni)
                    mma16h(e[mi][ni], A[mi][0], A[mi][1], A[mi][2], A[mi][3],
                           Bp[ni >> 1][(ni & 1) * 2], Bp[ni >> 1][(ni & 1) * 2 + 1]);
        }

        // ---- p = exp2(e - rl[n]) via ex2.f16x2; csum; store [n][m] ----
#pragma unroll
        for (int mi = 0; mi < 2; ++mi) {
            int r = row0 + mi * 16 + qr;
            float rlv0 = rl_s[r], rlv1 = rl_s[r + 8];
#pragma unroll
            for (int ni = 0; ni < 4; ++ni) {
                int col = col0 + ni * 8 + 2 * ql;
                half2 a01 = __floats2half2_rn(e[mi][ni][0] - rlv0, e[mi][ni][1] - rlv0);
                half2 a23 = __floats2half2_rn(e[mi][ni][2] - rlv1, e[mi][ni][3] - rlv1);
                uint32_t p01 = ex2h2(*(uint32_t*)&a01);
                uint32_t p23 = ex2h2(*(uint32_t*)&a23);
                *(uint32_t*)&pn_h[r * 72 + col]       = p01;
                *(uint32_t*)&pn_h[(r + 8) * 72 + col] = p23;
                half2 psum = __hadd2(*(half2*)&p01, *(half2*)&p23);
                float2 pf = __half22float2(psum);
                csum[ni * 2]     += pf.x;
                csum[ni * 2 + 1] += pf.y;
            }
        }
        CPA_WAIT(0);                 // vs(nt) ready
        __syncthreads();             // sync2: pn + vs visible; E/exp done w/ qn, rl

        if (nt + 1 < NN / 128) {     // prefetch {qn(nt+1), rl(nt+1)} — Y cover
#pragma unroll
            for (int k = 0; k < 2; ++k) {
                int idx = tid + k * 256;
                int r = idx >> 2, j = (idx & 3) << 3;
                cpa16(qn_u + (r * 40 + j) * 2,
                      &g_qh[((size_t)b * NN + nb + 128 + r) * DD + j]);
            }
            if (tid < 32) cpa16(rl_u + tid * 16, grl + nb + 128 + tid * 4);
            CPA_COMMIT();
        }

        // ---- Y += v @ p (fp16): warp 32x32, K=128 ----
#pragma unroll
        for (int ks = 0; ks < 8; ++ks) {
            const int k0 = ks * 16;
            uint32_t A[2][4], Bp[2][4];
#pragma unroll
            for (int mi = 0; mi < 2; ++mi)
                ldsm4(A[mi], vs_u + ((row0 + mi * 16 + la) * 136 + k0 + lc) * 2);
#pragma unroll
            for (int p = 0; p < 2; ++p)
                ldsm4t(Bp[p], pn_u + ((k0 + la) * 72 + col0 + p * 16 + lc) * 2);
#pragma unroll
            for (int mi = 0; mi < 2; ++mi)
#pragma unroll
                for (int ni = 0; ni < 4; ++ni)
                    mma16h(yacc[mi][ni], A[mi][0], A[mi][1], A[mi][2], A[mi][3],
                           Bp[ni >> 1][(ni & 1) * 2], Bp[ni >> 1][(ni & 1) * 2 + 1]);
        }
        __syncthreads();             // sync3: Y done with vs & pn
        if (nt + 1 < NN / 128) {     // prefetch {vs(nt+1)} — next E/exp cover
#pragma unroll
            for (int k = 0; k < 8; ++k) {
                int idx = tid + k * 256;
                int c = idx >> 4, j = (idx & 15) << 3;
                cpa16(vs_u + (c * 136 + j) * 2,
                      &g_v[((size_t)b * CC + c) * NN + nb + 128 + j]);
            }
            CPA_COMMIT();
        }
    }

    // ---------------- epilogue ----------------
#pragma unroll
    for (int i = 0; i < 8; ++i) {
        float v = csum[i];
        v += __shfl_xor_sync(0xffffffffu, v, 4);
        v += __shfl_xor_sync(0xffffffffu, v, 8);
        v += __shfl_xor_sync(0xffffffffu, v, 16);
        if (qr == 0) atomicAdd(&csum_s[col0 + (i >> 1) * 8 + 2 * ql + (i & 1)], v);
    }
    __syncthreads();   // all Y done (vs free), csum complete
    if (tid < 64) cinv_s[tid] = 1.0f / (1e-9f + csum_s[tid]);
    // stage wt fp16 into vs region: [cout][cin] stride 136
    for (int i = tid; i < CC * 64; i += 256) {
        int co = i >> 6, cp = (i & 63) << 1;
        float2 wv2 = *(const float2*)&wt[co * CC + cp];
        *(half2*)&wt_h[co * 136 + cp] = __floats2half2_rn(wv2.x, wv2.y);
    }
    __syncthreads();   // cinv visible

    // xm_h[m][c] = fp16(x - Y*cinv)  (overlays pn region)
    const float* xb = x + ((size_t)b * CC) * NN + m0;
#pragma unroll
    for (int mi = 0; mi < 2; ++mi) {
        int r = row0 + mi * 16 + qr;
#pragma unroll
        for (int ni = 0; ni < 4; ++ni) {
            int col = col0 + ni * 8 + 2 * ql;
            float2 x0 = __ldg((const float2*)&xb[(size_t)r * NN + col]);
            float2 x1 = __ldg((const float2*)&xb[(size_t)(r + 8) * NN + col]);
            float ci0 = cinv_s[col], ci1 = cinv_s[col + 1];
            xm_h[col * 136 + r]           = __float2half_rn(x0.x - yacc[mi][ni][0] * ci0);
            xm_h[(col + 1) * 136 + r]     = __float2half_rn(x0.y - yacc[mi][ni][1] * ci1);
            xm_h[col * 136 + r + 8]       = __float2half_rn(x1.x - yacc[mi][ni][2] * ci0);
            xm_h[(col + 1) * 136 + r + 8] = __float2half_rn(x1.y - yacc[mi][ni][3] * ci1);
        }
    }
    __syncthreads();   // wt_h + xm_h visible

    // t = wt @ xm  (fp16)
    float tacc[2][4][4] = {};
#pragma unroll
    for (int ks = 0; ks < 8; ++ks) {
        const int k0 = ks * 16;
        uint32_t A[2][4], Bp[2][4];
#pragma unroll
        for (int mi = 0; mi < 2; ++mi)
            ldsm4(A[mi], wt_u + ((row0 + mi * 16 + la) * 136 + k0 + lc) * 2);
#pragma unroll
        for (int p = 0; p < 2; ++p)
            ldsm4(Bp[p], xm_u + ((col0 + p * 16 + lbr) * 136 + k0 + lbc) * 2);
#pragma unroll
        for (int mi = 0; mi < 2; ++mi)
#pragma unroll
            for (int ni = 0; ni < 4; ++ni)
                mma16h(tacc[mi][ni], A[mi][0], A[mi][1], A[mi][2], A[mi][3],
                       Bp[ni >> 1][(ni & 1) * 2], Bp[ni >> 1][(ni & 1) * 2 + 1]);
    }

    // out = x + relu(t*A + S)
#pragma unroll
    for (int mi = 0; mi < 2; ++mi) {
        int r = row0 + mi * 16 + qr;
        float a0 = A_s[r], s0 = S_s[r];
        float a1 = A_s[r + 8], s1 = S_s[r + 8];
#pragma unroll
        for (int ni = 0; ni < 4; ++ni) {
            int col = col0 + ni * 8 + 2 * ql;
            float2 x0 = __ldg((const float2*)&xb[(size_t)r * NN + col]);
            float2 x1 = __ldg((const float2*)&xb[(size_t)(r + 8) * NN + col]);
            float2 o0, o1;
            o0.x = x0.x + fmaxf(fmaf(tacc[mi][ni][0], a0, s0), 0.f);
            o0.y = x0.y + fmaxf(fmaf(tacc[mi][ni][1], a0, s0), 0.f);
            o1.x = x1.x + fmaxf(fmaf(tacc[mi][ni][2], a1, s1), 0.f);
            o1.y = x1.y + fmaxf(fmaf(tacc[mi][ni][3], a1, s1), 0.f);
            *(float2*)&out[((size_t)b * CC + r) * NN + m0 + col]     = o0;
            *(float2*)&out[((size_t)b * CC + r + 8) * NN + m0 + col] = o1;
        }
    }
}

// ======================================================================
extern "C" void kernel_launch(void* const* d_in, const int* in_sizes, int n_in,
                              void* d_out, int out_size) {
    const float* x     = (const float*)d_in[0];
    const float* wq    = (const float*)d_in[1];
    const float* wv    = (const float*)d_in[2];
    const float* bv    = (const float*)d_in[3];
    const float* wt    = (const float*)d_in[4];
    const float* bt    = (const float*)d_in[5];
    const float* gamma = (const float*)d_in[6];
    const float* beta  = (const float*)d_in[7];
    const float* mean  = (const float*)d_in[8];
    const float* var   = (const float*)d_in[9];
    float* out = (float*)d_out;

    const int S1 = 95360;
    const int S2 = 128 * 4 + 3 * 128 * 40 * 2;   // 31232
    const int S3 = 70656;

    cudaFuncSetAttribute(k_qv,     cudaFuncAttributeMaxDynamicSharedMemorySize, S1);
    cudaFuncSetAttribute(k_rowsum, cudaFuncAttributeMaxDynamicSharedMemorySize, S2);
    cudaFuncSetAttribute(k_attn,   cudaFuncAttributeMaxDynamicSharedMemorySize, S3);

    k_qv<<<dim3(16, 16), 640, S1>>>(x, wq, wv, bv);
    k_rowsum<<<dim3(16, 16), 512, S2>>>();
    k_attn<<<dim3(32, 16), 256, S3>>>(x, wt, bt, gamma, beta, mean, var, out);
}

// round 16
// speedup vs baseline: 1.2435x; 1.2435x over previous
#include <cuda_runtime.h>
#include <cuda_fp16.h>
#include <cstdint>

#define BB 16
#define CC 128
#define DD 32
#define NN 2048
#define SQRT_LOG2E 1.2011224087864498f

// ---------------- device scratch (static) ----------------
__device__ __half g_qh[BB * NN * DD];   // qT[b][n][d], *sqrt(log2e), fp16
__device__ __half g_v [BB * CC * NN];   // v[b][c][n], fp16
__device__ float  g_rs[BB * NN];        // raw rowsums (zeroed by k1, accumulated by k2)

// ---------------- helpers ----------------
__device__ __forceinline__ float ex2f(float x) {
    float y; asm("ex2.approx.ftz.f32 %0, %1;" : "=f"(y) : "f"(x)); return y;
}
__device__ __forceinline__ float lg2f(float x) {
    float y; asm("lg2.approx.f32 %0, %1;" : "=f"(y) : "f"(x)); return y;
}
__device__ __forceinline__ void mma16h(float c[4],
                                       uint32_t a0, uint32_t a1, uint32_t a2, uint32_t a3,
                                       uint32_t b0, uint32_t b1) {
    asm volatile(
        "mma.sync.aligned.m16n8k16.row.col.f32.f16.f16.f32 "
        "{%0,%1,%2,%3}, {%4,%5,%6,%7}, {%8,%9}, {%0,%1,%2,%3};"
        : "+f"(c[0]), "+f"(c[1]), "+f"(c[2]), "+f"(c[3])
        : "r"(a0), "r"(a1), "r"(a2), "r"(a3), "r"(b0), "r"(b1));
}
__device__ __forceinline__ void ldsm4(uint32_t r[4], uint32_t addr) {
    asm volatile("ldmatrix.sync.aligned.m8n8.x4.shared.b16 {%0,%1,%2,%3}, [%4];"
        : "=r"(r[0]), "=r"(r[1]), "=r"(r[2]), "=r"(r[3]) : "r"(addr));
}
__device__ __forceinline__ void ldsm4t(uint32_t r[4], uint32_t addr) {
    asm volatile("ldmatrix.sync.aligned.m8n8.x4.trans.shared.b16 {%0,%1,%2,%3}, [%4];"
        : "=r"(r[0]), "=r"(r[1]), "=r"(r[2]), "=r"(r[3]) : "r"(addr));
}
__device__ __forceinline__ uint32_t smem_u32(const void* p) {
    uint32_t a;
    asm("{ .reg .u64 t; cvta.to.shared.u64 t, %1; cvt.u32.u64 %0, t; }" : "=r"(a) : "l"(p));
    return a;
}
__device__ __forceinline__ void cpa16(uint32_t dst, const void* src) {
    asm volatile("cp.async.cg.shared.global [%0], [%1], 16;" :: "r"(dst), "l"(src));
}
#define CPA_COMMIT() asm volatile("cp.async.commit_group;" ::: "memory")
#define CPA_WAIT(n)  asm volatile("cp.async.wait_group %0;" :: "n"(n) : "memory")

// ======================================================================
// k1: q = wq@x (scaled, fp16) ; v = wv@x + bv (fp16) — fp16 mma compute
// (R11 version — measured 26.8us) + zeroes g_rs slice for k2 accumulation.
// ======================================================================
__global__ __launch_bounds__(640) void k_qv(const float* __restrict__ x,
                                            const float* __restrict__ wq,
                                            const float* __restrict__ wv,
                                            const float* __restrict__ bv) {
    extern __shared__ char smc[];
    __half* xh   = (__half*)smc;              // [n][c] stride 136
    __half* wsh  = (__half*)(smc + 34816);    // [r][c] stride 136
    float*  qb   = (float*)(smc + 78336);     // 32x129
    float*  bv_s = (float*)(smc + 94848);
    const int b  = blockIdx.y;
    const int n0 = blockIdx.x * 128;
    const int tid = threadIdx.x;
    const float* xb = x + (size_t)b * CC * NN;

    if (tid < 128) g_rs[(size_t)b * NN + n0 + tid] = 0.f;

    for (int i = tid; i < CC * 128; i += 640) {
        int c = i >> 7, n = i & 127;
        xh[n * 136 + c] = __float2half_rn(xb[(size_t)c * NN + n0 + n]);
    }
    for (int i = tid; i < 160 * 128; i += 640) {
        int r = i >> 7, c = i & 127;
        float w = (r < DD) ? wq[r * CC + c] : wv[(r - DD) * CC + c];
        wsh[r * 136 + c] = __float2half_rn(w);
    }
    if (tid < CC) bv_s[tid] = bv[tid];
    __syncthreads();

    const int w = tid >> 5, lane = tid & 31;
    const int rg = w >> 2, cg = w & 3;
    const int row0 = rg * 32, col0 = cg * 32;
    const int qr = lane >> 2, ql = lane & 3;
    const uint32_t ws_u = smem_u32(wsh), xh_u = smem_u32(xh);
    const int la = ((lane >> 3) & 1) * 8 + (lane & 7);
    const int lc = (lane >> 4) * 8;
    const int lbr = (lane >> 4) * 8 + (lane & 7);
    const int lbc = ((lane >> 3) & 1) * 8;

    float acc[2][4][4] = {};
#pragma unroll
    for (int ks = 0; ks < 8; ++ks) {
        const int k0 = ks * 16;
        uint32_t A[2][4], Bp[2][4];
#pragma unroll
        for (int mi = 0; mi < 2; ++mi)
            ldsm4(A[mi], ws_u + ((row0 + mi * 16 + la) * 136 + k0 + lc) * 2);
#pragma unroll
        for (int p = 0; p < 2; ++p)
            ldsm4(Bp[p], xh_u + ((col0 + p * 16 + lbr) * 136 + k0 + lbc) * 2);
#pragma unroll
        for (int mi = 0; mi < 2; ++mi)
#pragma unroll
            for (int ni = 0; ni < 4; ++ni)
                mma16h(acc[mi][ni], A[mi][0], A[mi][1], A[mi][2], A[mi][3],
                       Bp[ni >> 1][(ni & 1) * 2], Bp[ni >> 1][(ni & 1) * 2 + 1]);
    }

    if (rg == 0) {
#pragma unroll
        for (int mi = 0; mi < 2; ++mi) {
            int d = mi * 16 + qr;
#pragma unroll
            for (int ni = 0; ni < 4; ++ni) {
                int col = col0 + ni * 8 + 2 * ql;
                qb[d * 129 + col]           = acc[mi][ni][0] * SQRT_LOG2E;
                qb[d * 129 + col + 1]       = acc[mi][ni][1] * SQRT_LOG2E;
                qb[(d + 8) * 129 + col]     = acc[mi][ni][2] * SQRT_LOG2E;
                qb[(d + 8) * 129 + col + 1] = acc[mi][ni][3] * SQRT_LOG2E;
            }
        }
    } else {
#pragma unroll
        for (int mi = 0; mi < 2; ++mi) {
            int rv = row0 - DD + mi * 16 + qr;
            float b0v = bv_s[rv], b1v = bv_s[rv + 8];
#pragma unroll
            for (int ni = 0; ni < 4; ++ni) {
                int col = col0 + ni * 8 + 2 * ql;
                *(half2*)&g_v[((size_t)b * CC + rv) * NN + n0 + col] =
                    __floats2half2_rn(acc[mi][ni][0] + b0v, acc[mi][ni][1] + b0v);
                *(half2*)&g_v[((size_t)b * CC + rv + 8) * NN + n0 + col] =
                    __floats2half2_rn(acc[mi][ni][2] + b1v, acc[mi][ni][3] + b1v);
            }
        }
    }
    __syncthreads();
    for (int i = tid; i < 128 * 16; i += 640) {
        int n = i >> 4, d2 = (i & 15) << 1;
        *(half2*)&g_qh[((size_t)b * NN + n0 + n) * DD + d2] =
            __floats2half2_rn(qb[d2 * 129 + n], qb[(d2 + 1) * 129 + n]);
    }
}

// ======================================================================
// k2: symmetric rowsum. E = q q^T is symmetric, so only the upper
// triangle of 128x128 tile-pairs (i <= j) is computed: tile rowsums
// feed rows in i, tile colsums feed rows in j (skip colsums when i==j).
// Partial sums accumulate into g_rs via atomics. fp32 exp REQUIRED
// (fp16 exp biases rowsums low; rl errors do not cancel).
// grid (136, 16), 512 threads (16 warps, 32x32 warp tiles).
// ======================================================================
__global__ __launch_bounds__(512, 2) void k_rowsum() {
    extern __shared__ float sm[];
    float*  red    = sm;                       // 128
    float*  colred = sm + 128;                 // 128
    __half* qi     = (__half*)(sm + 256);      // 128x40 h
    __half* qj     = qi + 128 * 40;            // 128x40 h

    const int tid = threadIdx.x, w = tid >> 5, lane = tid & 31;
    const int row0 = (w & 3) * 32, col0 = (w >> 2) * 32;
    const int qr = lane >> 2, ql = lane & 3;
    const int b = blockIdx.y;
    // decode triangular pair (i <= j) from blockIdx.x in [0, 136)
    int k = blockIdx.x, i = 0;
    while (k >= 16 - i) { k -= 16 - i; ++i; }
    const int j = i + k;
    const int diag = (i == j);

    const uint32_t qi_u = smem_u32(qi), qj_u = smem_u32(qj);
    const int la = ((lane >> 3) & 1) * 8 + (lane & 7);
    const int lc = (lane >> 4) * 8;
    const int lbr = (lane >> 4) * 8 + (lane & 7);
    const int lbc = ((lane >> 3) & 1) * 8;

    if (tid < 128) { red[tid] = 0.f; colred[tid] = 0.f; }
    {
        int r = tid >> 2, c8 = (tid & 3) << 3;
        cpa16(qi_u + (r * 40 + c8) * 2, &g_qh[((size_t)b * NN + i * 128 + r) * DD + c8]);
        cpa16(qj_u + (r * 40 + c8) * 2, &g_qh[((size_t)b * NN + j * 128 + r) * DD + c8]);
    }
    CPA_COMMIT();
    CPA_WAIT(0);
    __syncthreads();

    // ---- E tile: rows = i-tile, cols = j-tile (fp16 mma) ----
    float e[2][4][4] = {};
#pragma unroll
    for (int ks = 0; ks < 2; ++ks) {
        const int k0 = ks * 16;
        uint32_t A[2][4], Bp[2][4];
#pragma unroll
        for (int mi = 0; mi < 2; ++mi)
            ldsm4(A[mi], qi_u + ((row0 + mi * 16 + la) * 40 + k0 + lc) * 2);
#pragma unroll
        for (int p = 0; p < 2; ++p)
            ldsm4(Bp[p], qj_u + ((col0 + p * 16 + lbr) * 40 + k0 + lbc) * 2);
#pragma unroll
        for (int mi = 0; mi < 2; ++mi)
#pragma unroll
            for (int ni = 0; ni < 4; ++ni)
                mma16h(e[mi][ni], A[mi][0], A[mi][1], A[mi][2], A[mi][3],
                       Bp[ni >> 1][(ni & 1) * 2], Bp[ni >> 1][(ni & 1) * 2 + 1]);
    }

    // ---- exp (fp32) + row partials + col partials ----
    float racc[2][2] = {};
#pragma unroll
    for (int ni = 0; ni < 4; ++ni) {
        float c0 = 0.f, c1 = 0.f;
#pragma unroll
        for (int mi = 0; mi < 2; ++mi) {
            float p0 = ex2f(e[mi][ni][0]);
            float p1 = ex2f(e[mi][ni][1]);
            float p2 = ex2f(e[mi][ni][2]);
            float p3 = ex2f(e[mi][ni][3]);
            racc[mi][0] += p0 + p1;
            racc[mi][1] += p2 + p3;
            c0 += p0 + p2;
            c1 += p1 + p3;
        }
        if (!diag) {   // column sums -> rows of j-tile (reduce over qr)
            c0 += __shfl_xor_sync(0xffffffffu, c0, 4);
            c0 += __shfl_xor_sync(0xffffffffu, c0, 8);
            c0 += __shfl_xor_sync(0xffffffffu, c0, 16);
            c1 += __shfl_xor_sync(0xffffffffu, c1, 4);
            c1 += __shfl_xor_sync(0xffffffffu, c1, 8);
            c1 += __shfl_xor_sync(0xffffffffu, c1, 16);
            if (qr == 0) {
                atomicAdd(&colred[col0 + ni * 8 + 2 * ql],     c0);
                atomicAdd(&colred[col0 + ni * 8 + 2 * ql + 1], c1);
            }
        }
    }
    // row sums (reduce over ql)
#pragma unroll
    for (int mi = 0; mi < 2; ++mi)
#pragma unroll
        for (int h = 0; h < 2; ++h) {
            float v = racc[mi][h];
            v += __shfl_xor_sync(0xffffffffu, v, 1);
            v += __shfl_xor_sync(0xffffffffu, v, 2);
            racc[mi][h] = v;
        }
    if (ql == 0) {
        atomicAdd(&red[row0 + qr],          racc[0][0]);
        atomicAdd(&red[row0 + qr + 8],      racc[0][1]);
        atomicAdd(&red[row0 + 16 + qr],     racc[1][0]);
        atomicAdd(&red[row0 + 16 + qr + 8], racc[1][1]);
    }
    __syncthreads();
    if (tid < 128) {
        atomicAdd(&g_rs[(size_t)b * NN + i * 128 + tid], red[tid]);
        if (!diag)
            atomicAdd(&g_rs[(size_t)b * NN + j * 128 + tid], colred[tid]);
    }
}

// ======================================================================
// k3: fused attention + epilogue. (R11 version — measured best; 256 thr,
// m-tile 64, n-tile 128, 2 CTAs/SM, vs+rl double-buffered, fp32 exp.)
// rl buffers now hold RAW sums; lg2 applied at use.
// ======================================================================
__global__ __launch_bounds__(256, 2) void k_attn(const float* __restrict__ x,
                                                 const float* __restrict__ wt,
                                                 const float* __restrict__ bt,
                                                 const float* __restrict__ gamma,
                                                 const float* __restrict__ beta,
                                                 const float* __restrict__ mean,
                                                 const float* __restrict__ var,
                                                 float* __restrict__ out) {
    extern __shared__ float sm[];
    char* smc = (char*)sm;
    float* csum_s = sm;             // 64
    float* cinv_s = sm + 64;        // 64
    float* A_s    = sm + 128;       // 128
    float* S_s    = sm + 256;       // 128
    float* rl0_s  = sm + 384;       // 128
    float* rl1_s  = sm + 512;       // 128
    __half* qm_h  = (__half*)(smc + 3584);
    __half* qn_h  = (__half*)(smc + 8704);
    __half* vs0   = (__half*)(smc + 18944);
    __half* vs1   = (__half*)(smc + 53760);
    __half* pn_h  = (__half*)(smc + 88576);
    __half* wt_h  = vs0;                      // epilogue overlay
    __half* xm_h  = vs1;                      // epilogue overlay

    const int tid = threadIdx.x, w = tid >> 5, lane = tid & 31;
    const int row0 = (w & 3) * 32, col0 = (w >> 2) * 32;   // col0 in {0,32}
    const int qr = lane >> 2, ql = lane & 3;
    const int b = blockIdx.y, m0 = blockIdx.x * 64;
    const uint32_t qm_u = smem_u32(qm_h), qn_u = smem_u32(qn_h);
    const uint32_t vs0_u = smem_u32(vs0), vs1_u = smem_u32(vs1);
    const uint32_t pn_u = smem_u32(pn_h);
    const uint32_t rl0_u = smem_u32(rl0_s), rl1_u = smem_u32(rl1_s);
    const uint32_t wt_u = vs0_u, xm_u = vs1_u;
    const int la = ((lane >> 3) & 1) * 8 + (lane & 7);
    const int lc = (lane >> 4) * 8;
    const int lbr = (lane >> 4) * 8 + (lane & 7);
    const int lbc = ((lane >> 3) & 1) * 8;
    const float* grl = &g_rs[(size_t)b * NN];

    if (tid < 64) csum_s[tid] = 0.f;
    if (tid >= 64 && tid < 192) {
        int c = tid - 64;
        float A = gamma[c] * rsqrtf(var[c] + 1e-5f);
        A_s[c] = A;
        S_s[c] = beta[c] + (bt[c] - mean[c]) * A;
    }
    {   // qm: 64 rows x 32 halves
        int r = tid >> 2, j = (tid & 3) << 3;
        *(uint4*)&qm_h[r * 40 + j] =
            *(const uint4*)&g_qh[((size_t)b * NN + m0 + r) * DD + j];
    }
    // prologue: G1 = vs(0)->vs0 + rl(0)->rl0 ; G2 = qn(0)
#pragma unroll
    for (int k = 0; k < 8; ++k) {
        int idx = tid + k * 256;
        int c = idx >> 4, j = (idx & 15) << 3;
        cpa16(vs0_u + (c * 136 + j) * 2, &g_v[((size_t)b * CC + c) * NN + j]);
    }
    if (tid < 32) cpa16(rl0_u + tid * 16, grl + tid * 4);
    CPA_COMMIT();
#pragma unroll
    for (int k = 0; k < 2; ++k) {
        int idx = tid + k * 256;
        int r = idx >> 2, j = (idx & 3) << 3;
        cpa16(qn_u + (r * 40 + j) * 2, &g_qh[((size_t)b * NN + r) * DD + j]);
    }
    CPA_COMMIT();

    float yacc[2][4][4] = {};
    float csum[8] = {};

    for (int nt = 0; nt < NN / 128; ++nt) {
        const int nb = nt * 128;
        const uint32_t vcur = (nt & 1) ? vs1_u : vs0_u;
        const uint32_t valt = (nt & 1) ? vs0_u : vs1_u;
        const float*   rlc  = (nt & 1) ? rl1_s : rl0_s;
        const uint32_t rla  = (nt & 1) ? rl0_u : rl1_u;
        CPA_WAIT(0);                 // qn(nt), vs(nt), rl(nt) all ready
        __syncthreads();             // sync1: loads visible; prev Y done w/ pn

        // prefetch vs(nt+1) + rl(nt+1) — full-iteration cover
        if (nt + 1 < NN / 128) {
#pragma unroll
            for (int k = 0; k < 8; ++k) {
                int idx = tid + k * 256;
                int c = idx >> 4, j = (idx & 15) << 3;
                cpa16(valt + (c * 136 + j) * 2,
                      &g_v[((size_t)b * CC + c) * NN + nb + 128 + j]);
            }
            if (tid < 32) cpa16(rla + tid * 16, grl + nb + 128 + tid * 4);
            CPA_COMMIT();
        }

        // ---- E = qn . qm^T (fp16): warp 32x32 ----
        float e[2][4][4] = {};
#pragma unroll
        for (int ks = 0; ks < 2; ++ks) {
            const int k0 = ks * 16;
            uint32_t A[2][4], Bp[2][4];
#pragma unroll
            for (int mi = 0; mi < 2; ++mi)
                ldsm4(A[mi], qn_u + ((row0 + mi * 16 + la) * 40 + k0 + lc) * 2);
#pragma unroll
            for (int p = 0; p < 2; ++p)
                ldsm4(Bp[p], qm_u + ((col0 + p * 16 + lbr) * 40 + k0 + lbc) * 2);
#pragma unroll
            for (int mi = 0; mi < 2; ++mi)
#pragma unroll
                for (int ni = 0; ni < 4; ++ni)
                    mma16h(e[mi][ni], A[mi][0], A[mi][1], A[mi][2], A[mi][3],
                           Bp[ni >> 1][(ni & 1) * 2], Bp[ni >> 1][(ni & 1) * 2 + 1]);
        }

        // ---- p = exp2(e - log2(rs[n])); csum; store [n][m] fp16 ----
#pragma unroll
        for (int mi = 0; mi < 2; ++mi) {
            int r = row0 + mi * 16 + qr;
            float rlv0 = lg2f(rlc[r]), rlv1 = lg2f(rlc[r + 8]);
#pragma unroll
            for (int ni = 0; ni < 4; ++ni) {
                int col = col0 + ni * 8 + 2 * ql;
                float p00 = ex2f(e[mi][ni][0] - rlv0);
                float p01 = ex2f(e[mi][ni][1] - rlv0);
                float p10 = ex2f(e[mi][ni][2] - rlv1);
                float p11 = ex2f(e[mi][ni][3] - rlv1);
                csum[ni * 2]     += p00 + p10;
                csum[ni * 2 + 1] += p01 + p11;
                *(half2*)&pn_h[r * 72 + col]       = __floats2half2_rn(p00, p01);
                *(half2*)&pn_h[(r + 8) * 72 + col] = __floats2half2_rn(p10, p11);
            }
        }
        __syncthreads();             // sync2: pn visible; E done w/ qn

        if (nt + 1 < NN / 128) {     // prefetch qn(nt+1) — Y-phase cover
#pragma unroll
            for (int k = 0; k < 2; ++k) {
                int idx = tid + k * 256;
                int r = idx >> 2, j = (idx & 3) << 3;
                cpa16(qn_u + (r * 40 + j) * 2,
                      &g_qh[((size_t)b * NN + nb + 128 + r) * DD + j]);
            }
            CPA_COMMIT();
        }

        // ---- Y += v @ p (fp16): warp 32x32, K=128 ----
#pragma unroll
        for (int ks = 0; ks < 8; ++ks) {
            const int k0 = ks * 16;
            uint32_t A[2][4], Bp[2][4];
#pragma unroll
            for (int mi = 0; mi < 2; ++mi)
                ldsm4(A[mi], vcur + ((row0 + mi * 16 + la) * 136 + k0 + lc) * 2);
#pragma unroll
            for (int p = 0; p < 2; ++p)
                ldsm4t(Bp[p], pn_u + ((k0 + la) * 72 + col0 + p * 16 + lc) * 2);
#pragma unroll
            for (int mi = 0; mi < 2; ++mi)
#pragma unroll
                for (int ni = 0; ni < 4; ++ni)
                    mma16h(yacc[mi][ni], A[mi][0], A[mi][1], A[mi][2], A[mi][3],
                           Bp[ni >> 1][(ni & 1) * 2], Bp[ni >> 1][(ni & 1) * 2 + 1]);
        }
        // no end barrier: sync1 of next iter orders pn reuse; vs/rl double-buffered
    }

    // ---------------- epilogue ----------------
#pragma unroll
    for (int i = 0; i < 8; ++i) {
        float v = csum[i];
        v += __shfl_xor_sync(0xffffffffu, v, 4);
        v += __shfl_xor_sync(0xffffffffu, v, 8);
        v += __shfl_xor_sync(0xffffffffu, v, 16);
        if (qr == 0) atomicAdd(&csum_s[col0 + (i >> 1) * 8 + 2 * ql + (i & 1)], v);
    }
    __syncthreads();   // all Y done (vs free), csum complete
    if (tid < 64) cinv_s[tid] = 1.0f / (1e-9f + csum_s[tid]);
    // stage wt fp16 into vs0 region: [cout][cin] stride 136
    for (int i = tid; i < CC * 64; i += 256) {
        int co = i >> 6, cp = (i & 63) << 1;
        float2 wv2 = *(const float2*)&wt[co * CC + cp];
        *(half2*)&wt_h[co * 136 + cp] = __floats2half2_rn(wv2.x, wv2.y);
    }
    __syncthreads();   // cinv visible

    // xm_h[m][c] = fp16(x - Y*cinv)
    const float* xb = x + ((size_t)b * CC) * NN + m0;
#pragma unroll
    for (int mi = 0; mi < 2; ++mi) {
        int r = row0 + mi * 16 + qr;
#pragma unroll
        for (int ni = 0; ni < 4; ++ni) {
            int col = col0 + ni * 8 + 2 * ql;
            float2 x0 = __ldg((const float2*)&xb[(size_t)r * NN + col]);
            float2 x1 = __ldg((const float2*)&xb[(size_t)(r + 8) * NN + col]);
            float ci0 = cinv_s[col], ci1 = cinv_s[col + 1];
            xm_h[col * 136 + r]           = __float2half_rn(x0.x - yacc[mi][ni][0] * ci0);
            xm_h[(col + 1) * 136 + r]     = __float2half_rn(x0.y - yacc[mi][ni][1] * ci1);
            xm_h[col * 136 + r + 8]       = __float2half_rn(x1.x - yacc[mi][ni][2] * ci0);
            xm_h[(col + 1) * 136 + r + 8] = __float2half_rn(x1.y - yacc[mi][ni][3] * ci1);
        }
    }
    __syncthreads();   // wt_h + xm_h visible

    // t = wt @ xm  (fp16)
    float tacc[2][4][4] = {};
#pragma unroll
    for (int ks = 0; ks < 8; ++ks) {
        const int k0 = ks * 16;
        uint32_t A[2][4], Bp[2][4];
#pragma unroll
        for (int mi = 0; mi < 2; ++mi)
            ldsm4(A[mi], wt_u + ((row0 + mi * 16 + la) * 136 + k0 + lc) * 2);
#pragma unroll
        for (int p = 0; p < 2; ++p)
            ldsm4(Bp[p], xm_u + ((col0 + p * 16 + lbr) * 136 + k0 + lbc) * 2);
#pragma unroll
        for (int mi = 0; mi < 2; ++mi)
#pragma unroll
            for (int ni = 0; ni < 4; ++ni)
                mma16h(tacc[mi][ni], A[mi][0], A[mi][1], A[mi][2], A[mi][3],
                       Bp[ni >> 1][(ni & 1) * 2], Bp[ni >> 1][(ni & 1) * 2 + 1]);
    }

    // out = x + relu(t*A + S)
#pragma unroll
    for (int mi = 0; mi < 2; ++mi) {
        int r = row0 + mi * 16 + qr;
        float a0 = A_s[r], s0 = S_s[r];
        float a1 = A_s[r + 8], s1 = S_s[r + 8];
#pragma unroll
        for (int ni = 0; ni < 4; ++ni) {
            int col = col0 + ni * 8 + 2 * ql;
            float2 x0 = __ldg((const float2*)&xb[(size_t)r * NN + col]);
            float2 x1 = __ldg((const float2*)&xb[(size_t)(r + 8) * NN + col]);
            float2 o0, o1;
            o0.x = x0.x + fmaxf(fmaf(tacc[mi][ni][0], a0, s0), 0.f);
            o0.y = x0.y + fmaxf(fmaf(tacc[mi][ni][1], a0, s0), 0.f);
            o1.x = x1.x + fmaxf(fmaf(tacc[mi][ni][2], a1, s1), 0.f);
            o1.y = x1.y + fmaxf(fmaf(tacc[mi][ni][3], a1, s1), 0.f);
            *(float2*)&out[((size_t)b * CC + r) * NN + m0 + col]     = o0;
            *(float2*)&out[((size_t)b * CC + r + 8) * NN + m0 + col] = o1;
        }
    }
}

// ======================================================================
extern "C" void kernel_launch(void* const* d_in, const int* in_sizes, int n_in,
                              void* d_out, int out_size) {
    const float* x     = (const float*)d_in[0];
    const float* wq    = (const float*)d_in[1];
    const float* wv    = (const float*)d_in[2];
    const float* bv    = (const float*)d_in[3];
    const float* wt    = (const float*)d_in[4];
    const float* bt    = (const float*)d_in[5];
    const float* gamma = (const float*)d_in[6];
    const float* beta  = (const float*)d_in[7];
    const float* mean  = (const float*)d_in[8];
    const float* var   = (const float*)d_in[9];
    float* out = (float*)d_out;

    const int S1 = 95360;
    const int S2 = 256 * 4 + 2 * 128 * 40 * 2;   // 21504
    const int S3 = 107008;

    cudaFuncSetAttribute(k_qv,     cudaFuncAttributeMaxDynamicSharedMemorySize, S1);
    cudaFuncSetAttribute(k_rowsum, cudaFuncAttributeMaxDynamicSharedMemorySize, S2);
    cudaFuncSetAttribute(k_attn,   cudaFuncAttributeMaxDynamicSharedMemorySize, S3);

    k_qv<<<dim3(16, 16), 640, S1>>>(x, wq, wv, bv);
    k_rowsum<<<dim3(136, 16), 512, S2>>>();
    k_attn<<<dim3(32, 16), 256, S3>>>(x, wt, bt, gamma, beta, mean, var, out);
}

// round 17
// speedup vs baseline: 1.3562x; 1.0906x over previous
#include <cuda_runtime.h>
#include <cuda_fp16.h>
#include <cstdint>

#define BB 16
#define CC 128
#define DD 32
#define NN 2048
#define SQRT_LOG2E 1.2011224087864498f

// ---------------- device scratch (static) ----------------
__device__ __half g_qh[BB * NN * DD];   // qT[b][n][d], *sqrt(log2e), fp16
__device__ __half g_v [BB * CC * NN];   // v[b][c][n], fp16
__device__ float  g_rs[BB * NN];        // raw rowsums (zeroed by k1, accumulated by k2)

// ---------------- helpers ----------------
__device__ __forceinline__ float ex2f(float x) {
    float y; asm("ex2.approx.ftz.f32 %0, %1;" : "=f"(y) : "f"(x)); return y;
}
__device__ __forceinline__ float lg2f(float x) {
    float y; asm("lg2.approx.f32 %0, %1;" : "=f"(y) : "f"(x)); return y;
}
__device__ __forceinline__ void mma16h(float c[4],
                                       uint32_t a0, uint32_t a1, uint32_t a2, uint32_t a3,
                                       uint32_t b0, uint32_t b1) {
    asm volatile(
        "mma.sync.aligned.m16n8k16.row.col.f32.f16.f16.f32 "
        "{%0,%1,%2,%3}, {%4,%5,%6,%7}, {%8,%9}, {%0,%1,%2,%3};"
        : "+f"(c[0]), "+f"(c[1]), "+f"(c[2]), "+f"(c[3])
        : "r"(a0), "r"(a1), "r"(a2), "r"(a3), "r"(b0), "r"(b1));
}
__device__ __forceinline__ void ldsm4(uint32_t r[4], uint32_t addr) {
    asm volatile("ldmatrix.sync.aligned.m8n8.x4.shared.b16 {%0,%1,%2,%3}, [%4];"
        : "=r"(r[0]), "=r"(r[1]), "=r"(r[2]), "=r"(r[3]) : "r"(addr));
}
__device__ __forceinline__ void ldsm4t(uint32_t r[4], uint32_t addr) {
    asm volatile("ldmatrix.sync.aligned.m8n8.x4.trans.shared.b16 {%0,%1,%2,%3}, [%4];"
        : "=r"(r[0]), "=r"(r[1]), "=r"(r[2]), "=r"(r[3]) : "r"(addr));
}
__device__ __forceinline__ uint32_t smem_u32(const void* p) {
    uint32_t a;
    asm("{ .reg .u64 t; cvta.to.shared.u64 t, %1; cvt.u32.u64 %0, t; }" : "=r"(a) : "l"(p));
    return a;
}
__device__ __forceinline__ void cpa16(uint32_t dst, const void* src) {
    asm volatile("cp.async.cg.shared.global [%0], [%1], 16;" :: "r"(dst), "l"(src));
}
#define CPA_COMMIT() asm volatile("cp.async.commit_group;" ::: "memory")
#define CPA_WAIT(n)  asm volatile("cp.async.wait_group %0;" :: "n"(n) : "memory")

// ======================================================================
// k1: q = wq@x (scaled, fp16) ; v = wv@x + bv (fp16) — fp16 mma compute
// (R11 version) + zeroes g_rs slice for k2 accumulation.
// ======================================================================
__global__ __launch_bounds__(640) void k_qv(const float* __restrict__ x,
                                            const float* __restrict__ wq,
                                            const float* __restrict__ wv,
                                            const float* __restrict__ bv) {
    extern __shared__ char smc[];
    __half* xh   = (__half*)smc;              // [n][c] stride 136
    __half* wsh  = (__half*)(smc + 34816);    // [r][c] stride 136
    float*  qb   = (float*)(smc + 78336);     // 32x129
    float*  bv_s = (float*)(smc + 94848);
    const int b  = blockIdx.y;
    const int n0 = blockIdx.x * 128;
    const int tid = threadIdx.x;
    const float* xb = x + (size_t)b * CC * NN;

    if (tid < 128) g_rs[(size_t)b * NN + n0 + tid] = 0.f;

    for (int i = tid; i < CC * 128; i += 640) {
        int c = i >> 7, n = i & 127;
        xh[n * 136 + c] = __float2half_rn(xb[(size_t)c * NN + n0 + n]);
    }
    for (int i = tid; i < 160 * 128; i += 640) {
        int r = i >> 7, c = i & 127;
        float w = (r < DD) ? wq[r * CC + c] : wv[(r - DD) * CC + c];
        wsh[r * 136 + c] = __float2half_rn(w);
    }
    if (tid < CC) bv_s[tid] = bv[tid];
    __syncthreads();

    const int w = tid >> 5, lane = tid & 31;
    const int rg = w >> 2, cg = w & 3;
    const int row0 = rg * 32, col0 = cg * 32;
    const int qr = lane >> 2, ql = lane & 3;
    const uint32_t ws_u = smem_u32(wsh), xh_u = smem_u32(xh);
    const int la = ((lane >> 3) & 1) * 8 + (lane & 7);
    const int lc = (lane >> 4) * 8;
    const int lbr = (lane >> 4) * 8 + (lane & 7);
    const int lbc = ((lane >> 3) & 1) * 8;

    float acc[2][4][4] = {};
#pragma unroll
    for (int ks = 0; ks < 8; ++ks) {
        const int k0 = ks * 16;
        uint32_t A[2][4], Bp[2][4];
#pragma unroll
        for (int mi = 0; mi < 2; ++mi)
            ldsm4(A[mi], ws_u + ((row0 + mi * 16 + la) * 136 + k0 + lc) * 2);
#pragma unroll
        for (int p = 0; p < 2; ++p)
            ldsm4(Bp[p], xh_u + ((col0 + p * 16 + lbr) * 136 + k0 + lbc) * 2);
#pragma unroll
        for (int mi = 0; mi < 2; ++mi)
#pragma unroll
            for (int ni = 0; ni < 4; ++ni)
                mma16h(acc[mi][ni], A[mi][0], A[mi][1], A[mi][2], A[mi][3],
                       Bp[ni >> 1][(ni & 1) * 2], Bp[ni >> 1][(ni & 1) * 2 + 1]);
    }

    if (rg == 0) {
#pragma unroll
        for (int mi = 0; mi < 2; ++mi) {
            int d = mi * 16 + qr;
#pragma unroll
            for (int ni = 0; ni < 4; ++ni) {
                int col = col0 + ni * 8 + 2 * ql;
                qb[d * 129 + col]           = acc[mi][ni][0] * SQRT_LOG2E;
                qb[d * 129 + col + 1]       = acc[mi][ni][1] * SQRT_LOG2E;
                qb[(d + 8) * 129 + col]     = acc[mi][ni][2] * SQRT_LOG2E;
                qb[(d + 8) * 129 + col + 1] = acc[mi][ni][3] * SQRT_LOG2E;
            }
        }
    } else {
#pragma unroll
        for (int mi = 0; mi < 2; ++mi) {
            int rv = row0 - DD + mi * 16 + qr;
            float b0v = bv_s[rv], b1v = bv_s[rv + 8];
#pragma unroll
            for (int ni = 0; ni < 4; ++ni) {
                int col = col0 + ni * 8 + 2 * ql;
                *(half2*)&g_v[((size_t)b * CC + rv) * NN + n0 + col] =
                    __floats2half2_rn(acc[mi][ni][0] + b0v, acc[mi][ni][1] + b0v);
                *(half2*)&g_v[((size_t)b * CC + rv + 8) * NN + n0 + col] =
                    __floats2half2_rn(acc[mi][ni][2] + b1v, acc[mi][ni][3] + b1v);
            }
        }
    }
    __syncthreads();
    for (int i = tid; i < 128 * 16; i += 640) {
        int n = i >> 4, d2 = (i & 15) << 1;
        *(half2*)&g_qh[((size_t)b * NN + n0 + n) * DD + d2] =
            __floats2half2_rn(qb[d2 * 129 + n], qb[(d2 + 1) * 129 + n]);
    }
}

// ======================================================================
// k2: symmetric rowsum (R16 version). fp32 exp REQUIRED.
// grid (136, 16), 512 threads.
// ======================================================================
__global__ __launch_bounds__(512, 2) void k_rowsum() {
    extern __shared__ float sm[];
    float*  red    = sm;                       // 128
    float*  colred = sm + 128;                 // 128
    __half* qi     = (__half*)(sm + 256);      // 128x40 h
    __half* qj     = qi + 128 * 40;            // 128x40 h

    const int tid = threadIdx.x, w = tid >> 5, lane = tid & 31;
    const int row0 = (w & 3) * 32, col0 = (w >> 2) * 32;
    const int qr = lane >> 2, ql = lane & 3;
    const int b = blockIdx.y;
    int k = blockIdx.x, i = 0;
    while (k >= 16 - i) { k -= 16 - i; ++i; }
    const int j = i + k;
    const int diag = (i == j);

    const uint32_t qi_u = smem_u32(qi), qj_u = smem_u32(qj);
    const int la = ((lane >> 3) & 1) * 8 + (lane & 7);
    const int lc = (lane >> 4) * 8;
    const int lbr = (lane >> 4) * 8 + (lane & 7);
    const int lbc = ((lane >> 3) & 1) * 8;

    if (tid < 128) { red[tid] = 0.f; colred[tid] = 0.f; }
    {
        int r = tid >> 2, c8 = (tid & 3) << 3;
        cpa16(qi_u + (r * 40 + c8) * 2, &g_qh[((size_t)b * NN + i * 128 + r) * DD + c8]);
        cpa16(qj_u + (r * 40 + c8) * 2, &g_qh[((size_t)b * NN + j * 128 + r) * DD + c8]);
    }
    CPA_COMMIT();
    CPA_WAIT(0);
    __syncthreads();

    float e[2][4][4] = {};
#pragma unroll
    for (int ks = 0; ks < 2; ++ks) {
        const int k0 = ks * 16;
        uint32_t A[2][4], Bp[2][4];
#pragma unroll
        for (int mi = 0; mi < 2; ++mi)
            ldsm4(A[mi], qi_u + ((row0 + mi * 16 + la) * 40 + k0 + lc) * 2);
#pragma unroll
        for (int p = 0; p < 2; ++p)
            ldsm4(Bp[p], qj_u + ((col0 + p * 16 + lbr) * 40 + k0 + lbc) * 2);
#pragma unroll
        for (int mi = 0; mi < 2; ++mi)
#pragma unroll
            for (int ni = 0; ni < 4; ++ni)
                mma16h(e[mi][ni], A[mi][0], A[mi][1], A[mi][2], A[mi][3],
                       Bp[ni >> 1][(ni & 1) * 2], Bp[ni >> 1][(ni & 1) * 2 + 1]);
    }

    float racc[2][2] = {};
#pragma unroll
    for (int ni = 0; ni < 4; ++ni) {
        float c0 = 0.f, c1 = 0.f;
#pragma unroll
        for (int mi = 0; mi < 2; ++mi) {
            float p0 = ex2f(e[mi][ni][0]);
            float p1 = ex2f(e[mi][ni][1]);
            float p2 = ex2f(e[mi][ni][2]);
            float p3 = ex2f(e[mi][ni][3]);
            racc[mi][0] += p0 + p1;
            racc[mi][1] += p2 + p3;
            c0 += p0 + p2;
            c1 += p1 + p3;
        }
        if (!diag) {
            c0 += __shfl_xor_sync(0xffffffffu, c0, 4);
            c0 += __shfl_xor_sync(0xffffffffu, c0, 8);
            c0 += __shfl_xor_sync(0xffffffffu, c0, 16);
            c1 += __shfl_xor_sync(0xffffffffu, c1, 4);
            c1 += __shfl_xor_sync(0xffffffffu, c1, 8);
            c1 += __shfl_xor_sync(0xffffffffu, c1, 16);
            if (qr == 0) {
                atomicAdd(&colred[col0 + ni * 8 + 2 * ql],     c0);
                atomicAdd(&colred[col0 + ni * 8 + 2 * ql + 1], c1);
            }
        }
    }
#pragma unroll
    for (int mi = 0; mi < 2; ++mi)
#pragma unroll
        for (int h = 0; h < 2; ++h) {
            float v = racc[mi][h];
            v += __shfl_xor_sync(0xffffffffu, v, 1);
            v += __shfl_xor_sync(0xffffffffu, v, 2);
            racc[mi][h] = v;
        }
    if (ql == 0) {
        atomicAdd(&red[row0 + qr],          racc[0][0]);
        atomicAdd(&red[row0 + qr + 8],      racc[0][1]);
        atomicAdd(&red[row0 + 16 + qr],     racc[1][0]);
        atomicAdd(&red[row0 + 16 + qr + 8], racc[1][1]);
    }
    __syncthreads();
    if (tid < 128) {
        atomicAdd(&g_rs[(size_t)b * NN + i * 128 + tid], red[tid]);
        if (!diag)
            atomicAdd(&g_rs[(size_t)b * NN + j * 128 + tid], colred[tid]);
    }
}

// ======================================================================
// k3: fused attention + epilogue. 256 threads, m-tile 128, n-tile 128,
// 2 CTAs/SM (92672 B smem), SINGLE WAVE (256 blocks / 296 slots).
// Warp tiles 32x64; yacc[2][8][4]=64 regs; E computed in 4 col-quarters
// (transient e = 16 regs). R9-style split waits: CPA_WAIT(1) top (qn+rl),
// CPA_WAIT(0) pre-Y (vs) — vs covered by full E+exp phase.
// smem: header 2560 | qm 10240 @2560 | qn 10240 @12800 |
//       vs 34816 @23040 (epi: wt_h) | pn 34816 @57856 (epi: xm_h)
// ======================================================================
__global__ __launch_bounds__(256, 2) void k_attn(const float* __restrict__ x,
                                                 const float* __restrict__ wt,
                                                 const float* __restrict__ bt,
                                                 const float* __restrict__ gamma,
                                                 const float* __restrict__ beta,
                                                 const float* __restrict__ mean,
                                                 const float* __restrict__ var,
                                                 float* __restrict__ out) {
    extern __shared__ float sm[];
    char* smc = (char*)sm;
    float* csum_s = sm;             // 128
    float* cinv_s = sm + 128;       // 128
    float* A_s    = sm + 256;       // 128
    float* S_s    = sm + 384;       // 128
    float* rl_s   = sm + 512;       // 128
    __half* qm_h  = (__half*)(smc + 2560);    // [m][d] stride 40
    __half* qn_h  = (__half*)(smc + 12800);   // [n][d] stride 40
    __half* vs    = (__half*)(smc + 23040);   // [c][n] stride 136
    __half* pn_h  = (__half*)(smc + 57856);   // [n][m] stride 136
    __half* wt_h  = vs;                       // epilogue overlay
    __half* xm_h  = pn_h;                     // epilogue overlay

    const int tid = threadIdx.x, w = tid >> 5, lane = tid & 31;
    const int row0 = (w & 3) * 32, col0 = (w >> 2) * 64;   // col0 in {0,64}
    const int qr = lane >> 2, ql = lane & 3;
    const int b = blockIdx.y, m0 = blockIdx.x * 128;
    const uint32_t qm_u = smem_u32(qm_h), qn_u = smem_u32(qn_h);
    const uint32_t vs_u = smem_u32(vs), pn_u = smem_u32(pn_h);
    const uint32_t rl_u = smem_u32(rl_s);
    const uint32_t wt_u = vs_u, xm_u = pn_u;
    const int la = ((lane >> 3) & 1) * 8 + (lane & 7);
    const int lc = (lane >> 4) * 8;
    const int lbr = (lane >> 4) * 8 + (lane & 7);
    const int lbc = ((lane >> 3) & 1) * 8;
    const float* grl = &g_rs[(size_t)b * NN];

    if (tid < 128) csum_s[tid] = 0.f;
    if (tid >= 128) {
        int c = tid - 128;
        float A = gamma[c] * rsqrtf(var[c] + 1e-5f);
        A_s[c] = A;
        S_s[c] = beta[c] + (bt[c] - mean[c]) * A;
    }
    {   // qm: 128 rows x 32 halves = 512 uint4 chunks
#pragma unroll
        for (int k = 0; k < 2; ++k) {
            int idx = tid + k * 256;
            int r = idx >> 2, j = (idx & 3) << 3;
            *(uint4*)&qm_h[r * 40 + j] =
                *(const uint4*)&g_qh[((size_t)b * NN + m0 + r) * DD + j];
        }
    }
    // prologue: G1 = {qn(0), rl(0)} ; G2 = {vs(0)}
#pragma unroll
    for (int k = 0; k < 2; ++k) {
        int idx = tid + k * 256;
        int r = idx >> 2, j = (idx & 3) << 3;
        cpa16(qn_u + (r * 40 + j) * 2, &g_qh[((size_t)b * NN + r) * DD + j]);
    }
    if (tid < 32) cpa16(rl_u + tid * 16, grl + tid * 4);
    CPA_COMMIT();
#pragma unroll
    for (int k = 0; k < 8; ++k) {
        int idx = tid + k * 256;
        int c = idx >> 4, j = (idx & 15) << 3;
        cpa16(vs_u + (c * 136 + j) * 2, &g_v[((size_t)b * CC + c) * NN + j]);
    }
    CPA_COMMIT();

    float yacc[2][8][4] = {};
    float csum[16] = {};

    for (int nt = 0; nt < NN / 128; ++nt) {
        const int nb = nt * 128;
        CPA_WAIT(1);                 // qn(nt) + rl(nt) ready; vs may fly
        __syncthreads();             // sync1: loads visible; prev Y done w/ pn

        // hoisted per-row log2(rowsum)
        float rlv[4];
        rlv[0] = lg2f(rl_s[row0 + qr]);
        rlv[1] = lg2f(rl_s[row0 + qr + 8]);
        rlv[2] = lg2f(rl_s[row0 + 16 + qr]);
        rlv[3] = lg2f(rl_s[row0 + 24 + qr]);

        // ---- E + exp in 4 col-quarters (16 cols each) ----
#pragma unroll
        for (int h = 0; h < 4; ++h) {
            const int colh = col0 + h * 16;
            float e[2][2][4] = {};
#pragma unroll
            for (int ks = 0; ks < 2; ++ks) {
                const int k0 = ks * 16;
                uint32_t A[2][4], Bq[4];
#pragma unroll
                for (int mi = 0; mi < 2; ++mi)
                    ldsm4(A[mi], qn_u + ((row0 + mi * 16 + la) * 40 + k0 + lc) * 2);
                ldsm4(Bq, qm_u + ((colh + lbr) * 40 + k0 + lbc) * 2);
#pragma unroll
                for (int mi = 0; mi < 2; ++mi)
#pragma unroll
                    for (int ni = 0; ni < 2; ++ni)
                        mma16h(e[mi][ni], A[mi][0], A[mi][1], A[mi][2], A[mi][3],
                               Bq[ni * 2], Bq[ni * 2 + 1]);
            }
#pragma unroll
            for (int mi = 0; mi < 2; ++mi) {
                int r = row0 + mi * 16 + qr;
                float rlv0 = rlv[mi * 2], rlv1 = rlv[mi * 2 + 1];
#pragma unroll
                for (int ni = 0; ni < 2; ++ni) {
                    int col = colh + ni * 8 + 2 * ql;
                    float p00 = ex2f(e[mi][ni][0] - rlv0);
                    float p01 = ex2f(e[mi][ni][1] - rlv0);
                    float p10 = ex2f(e[mi][ni][2] - rlv1);
                    float p11 = ex2f(e[mi][ni][3] - rlv1);
                    csum[h * 4 + ni * 2]     += p00 + p10;
                    csum[h * 4 + ni * 2 + 1] += p01 + p11;
                    *(half2*)&pn_h[r * 136 + col]       = __floats2half2_rn(p00, p01);
                    *(half2*)&pn_h[(r + 8) * 136 + col] = __floats2half2_rn(p10, p11);
                }
            }
        }
        CPA_WAIT(0);                 // vs(nt) ready
        __syncthreads();             // sync2: pn + vs visible; E done w/ qn, rl

        if (nt + 1 < NN / 128) {     // prefetch {qn(nt+1), rl(nt+1)} — Y cover
#pragma unroll
            for (int k = 0; k < 2; ++k) {
                int idx = tid + k * 256;
                int r = idx >> 2, j = (idx & 3) << 3;
                cpa16(qn_u + (r * 40 + j) * 2,
                      &g_qh[((size_t)b * NN + nb + 128 + r) * DD + j]);
            }
            if (tid < 32) cpa16(rl_u + tid * 16, grl + nb + 128 + tid * 4);
            CPA_COMMIT();
        }

        // ---- Y += v @ p (fp16): warp 32c x 64m, K=128 ----
#pragma unroll
        for (int ks = 0; ks < 8; ++ks) {
            const int k0 = ks * 16;
            uint32_t A[2][4];
#pragma unroll
            for (int mi = 0; mi < 2; ++mi)
                ldsm4(A[mi], vs_u + ((row0 + mi * 16 + la) * 136 + k0 + lc) * 2);
#pragma unroll
            for (int p = 0; p < 4; ++p) {
                uint32_t Bp[4];
                ldsm4t(Bp, pn_u + ((k0 + la) * 136 + col0 + p * 16 + lc) * 2);
#pragma unroll
                for (int mi = 0; mi < 2; ++mi) {
                    mma16h(yacc[mi][p * 2],     A[mi][0], A[mi][1], A[mi][2], A[mi][3],
                           Bp[0], Bp[1]);
                    mma16h(yacc[mi][p * 2 + 1], A[mi][0], A[mi][1], A[mi][2], A[mi][3],
                           Bp[2], Bp[3]);
                }
            }
        }
        __syncthreads();             // sync3: Y done with vs & pn
        if (nt + 1 < NN / 128) {     // prefetch {vs(nt+1)} — next E+exp cover
#pragma unroll
            for (int k = 0; k < 8; ++k) {
                int idx = tid + k * 256;
                int c = idx >> 4, j = (idx & 15) << 3;
                cpa16(vs_u + (c * 136 + j) * 2,
                      &g_v[((size_t)b * CC + c) * NN + nb + 128 + j]);
            }
            CPA_COMMIT();
        }
    }

    // ---------------- epilogue ----------------
#pragma unroll
    for (int i = 0; i < 16; ++i) {
        float v = csum[i];
        v += __shfl_xor_sync(0xffffffffu, v, 4);
        v += __shfl_xor_sync(0xffffffffu, v, 8);
        v += __shfl_xor_sync(0xffffffffu, v, 16);
        if (qr == 0)
            atomicAdd(&csum_s[col0 + (i >> 2) * 16 + ((i >> 1) & 1) * 8 + 2 * ql + (i & 1)], v);
    }
    __syncthreads();   // all Y done (vs free), csum complete
    if (tid < 128) cinv_s[tid] = 1.0f / (1e-9f + csum_s[tid]);
    // stage wt fp16 into vs region: [cout][cin] stride 136
    for (int i = tid; i < CC * 64; i += 256) {
        int co = i >> 6, cp = (i & 63) << 1;
        float2 wv2 = *(const float2*)&wt[co * CC + cp];
        *(half2*)&wt_h[co * 136 + cp] = __floats2half2_rn(wv2.x, wv2.y);
    }
    __syncthreads();   // cinv visible

    // xm_h[m][c] = fp16(x - Y*cinv)  (overlays pn region)
    const float* xb = x + ((size_t)b * CC) * NN + m0;
#pragma unroll
    for (int mi = 0; mi < 2; ++mi) {
        int r = row0 + mi * 16 + qr;
#pragma unroll
        for (int ni = 0; ni < 8; ++ni) {
            int col = col0 + ni * 8 + 2 * ql;
            float2 x0 = __ldg((const float2*)&xb[(size_t)r * NN + col]);
            float2 x1 = __ldg((const float2*)&xb[(size_t)(r + 8) * NN + col]);
            float ci0 = cinv_s[col], ci1 = cinv_s[col + 1];
            xm_h[col * 136 + r]           = __float2half_rn(x0.x - yacc[mi][ni][0] * ci0);
            xm_h[(col + 1) * 136 + r]     = __float2half_rn(x0.y - yacc[mi][ni][1] * ci1);
            xm_h[col * 136 + r + 8]       = __float2half_rn(x1.x - yacc[mi][ni][2] * ci0);
            xm_h[(col + 1) * 136 + r + 8] = __float2half_rn(x1.y - yacc[mi][ni][3] * ci1);
        }
    }
    __syncthreads();   // wt_h + xm_h visible

    // t = wt @ xm  (fp16): warp 32co x 64m
    float tacc[2][8][4] = {};
#pragma unroll
    for (int ks = 0; ks < 8; ++ks) {
        const int k0 = ks * 16;
        uint32_t A[2][4];
#pragma unroll
        for (int mi = 0; mi < 2; ++mi)
            ldsm4(A[mi], wt_u + ((row0 + mi * 16 + la) * 136 + k0 + lc) * 2);
#pragma unroll
        for (int p = 0; p < 4; ++p) {
            uint32_t Bp[4];
            ldsm4(Bp, xm_u + ((col0 + p * 16 + lbr) * 136 + k0 + lbc) * 2);
#pragma unroll
            for (int mi = 0; mi < 2; ++mi) {
                mma16h(tacc[mi][p * 2],     A[mi][0], A[mi][1], A[mi][2], A[mi][3],
                       Bp[0], Bp[1]);
                mma16h(tacc[mi][p * 2 + 1], A[mi][0], A[mi][1], A[mi][2], A[mi][3],
                       Bp[2], Bp[3]);
            }
        }
    }

    // out = x + relu(t*A + S)
#pragma unroll
    for (int mi = 0; mi < 2; ++mi) {
        int r = row0 + mi * 16 + qr;
        float a0 = A_s[r], s0 = S_s[r];
        float a1 = A_s[r + 8], s1 = S_s[r + 8];
#pragma unroll
        for (int ni = 0; ni < 8; ++ni) {
            int col = col0 + ni * 8 + 2 * ql;
            float2 x0 = __ldg((const float2*)&xb[(size_t)r * NN + col]);
            float2 x1 = __ldg((const float2*)&xb[(size_t)(r + 8) * NN + col]);
            float2 o0, o1;
            o0.x = x0.x + fmaxf(fmaf(tacc[mi][ni][0], a0, s0), 0.f);
            o0.y = x0.y + fmaxf(fmaf(tacc[mi][ni][1], a0, s0), 0.f);
            o1.x = x1.x + fmaxf(fmaf(tacc[mi][ni][2], a1, s1), 0.f);
            o1.y = x1.y + fmaxf(fmaf(tacc[mi][ni][3], a1, s1), 0.f);
            *(float2*)&out[((size_t)b * CC + r) * NN + m0 + col]     = o0;
            *(float2*)&out[((size_t)b * CC + r + 8) * NN + m0 + col] = o1;
        }
    }
}

// ======================================================================
extern "C" void kernel_launch(void* const* d_in, const int* in_sizes, int n_in,
                              void* d_out, int out_size) {
    const float* x     = (const float*)d_in[0];
    const float* wq    = (const float*)d_in[1];
    const float* wv    = (const float*)d_in[2];
    const float* bv    = (const float*)d_in[3];
    const float* wt    = (const float*)d_in[4];
    const float* bt    = (const float*)d_in[5];
    const float* gamma = (const float*)d_in[6];
    const float* beta  = (const float*)d_in[7];
    const float* mean  = (const float*)d_in[8];
    const float* var   = (const float*)d_in[9];
    float* out = (float*)d_out;

    const int S1 = 95360;
    const int S2 = 256 * 4 + 2 * 128 * 40 * 2;   // 21504
    const int S3 = 92672;

    cudaFuncSetAttribute(k_qv,     cudaFuncAttributeMaxDynamicSharedMemorySize, S1);
    cudaFuncSetAttribute(k_rowsum, cudaFuncAttributeMaxDynamicSharedMemorySize, S2);
    cudaFuncSetAttribute(k_attn,   cudaFuncAttributeMaxDynamicSharedMemorySize, S3);

    k_qv<<<dim3(16, 16), 640, S1>>>(x, wq, wv, bv);
    k_rowsum<<<dim3(136, 16), 512, S2>>>();
    k_attn<<<dim3(16, 16), 256, S3>>>(x, wt, bt, gamma, beta, mean, var, out);
}